// round 14
// baseline (speedup 1.0000x reference)
#include <cuda_runtime.h>
#include <math.h>
#include <float.h>
#include <stdint.h>

#define TT   80
#define DIN  4096
#define HH   512
#define HD2  1024
#define GE   2048      /* 4*HH  */
#define VV   32000
#define KB   4
#define ML   20
#define NB   148
#define NT   256
#define NWARP (NB*8)   /* 1184 */

#define TR      24                       /* W_out tile rows */
#define NTILES  ((VV + TR - 1) / TR)     /* 1334 */
#define OS_F4   1024                     /* os: 4 beams x 256 float4 */
#define DYN_FLOATS (4*OS_F4 + 2*TR*HD2)  /* 4096 + 49152 = 53248 floats */
#define DYN_BYTES  (DYN_FLOATS*4)        /* 212992 B */

// ---------------- device scratch ----------------
__device__ float g_Xpre[TT*GE];
__device__ float g_Gb[GE];
__device__ float g_encH[2][HH];
__device__ float g_encC[HH];
__device__ float g_h2[2][KB*HD2];
__device__ float g_c2[2][KB*HD2];
__device__ float g_o[KB*HD2];
__device__ float g_logits[KB*VV];
__device__ int   g_tok[2][KB*(ML+1)];
__device__ float g_pmax[NB*KB];
__device__ float g_psum[NB*KB];
__device__ float g_candv[NB*KB];
__device__ int   g_candi[NB*KB];
__device__ unsigned g_cnt = 0;
__device__ volatile unsigned g_epoch = 0;
__device__ unsigned g_cnt_e = 0;
__device__ volatile unsigned g_epoch_e = 0;

// ---------------- helpers ----------------
__device__ __forceinline__ float sigm(float x){ return 1.f/(1.f+expf(-x)); }
__device__ __forceinline__ float dot4(float4 a, float4 b){
    return a.x*b.x + a.y*b.y + a.z*b.z + a.w*b.w;
}
__device__ __forceinline__ float ftz(float x){
    return (fabsf(x) < FLT_MIN) ? 0.f : x;
}
__device__ __forceinline__ void cpa16(void* sdst, const void* gsrc){
    unsigned sa = (unsigned)__cvta_generic_to_shared(sdst);
    asm volatile("cp.async.cg.shared.global [%0], [%1], 16;" :: "r"(sa), "l"(gsrc));
}

__device__ __forceinline__ bool bet(float v1,int i1,float v2,int i2){
    return (v1 > v2) || (v1 == v2 && i1 < i2);
}
__device__ __forceinline__ void ins4(float v,int i,float tv[4],int ti[4]){
    if (bet(v,i,tv[3],ti[3])){
        tv[3]=v; ti[3]=i;
        if (bet(tv[3],ti[3],tv[2],ti[2])){ float a=tv[2];int b=ti[2]; tv[2]=tv[3];ti[2]=ti[3]; tv[3]=a;ti[3]=b; }
        if (bet(tv[2],ti[2],tv[1],ti[1])){ float a=tv[1];int b=ti[1]; tv[1]=tv[2];ti[1]=ti[2]; tv[2]=a;ti[2]=b; }
        if (bet(tv[1],ti[1],tv[0],ti[0])){ float a=tv[0];int b=ti[0]; tv[0]=tv[1];ti[0]=ti[1]; tv[1]=a;ti[1]=b; }
    }
}
__device__ __forceinline__ void warp_merge4(float tv[4],int ti[4]){
    #pragma unroll
    for (int off=16; off; off>>=1){
        float ov[4]; int oi[4];
        #pragma unroll
        for (int j=0;j<4;j++){
            ov[j]=__shfl_xor_sync(0xffffffffu,tv[j],off);
            oi[j]=__shfl_xor_sync(0xffffffffu,ti[j],off);
        }
        #pragma unroll
        for (int j=0;j<4;j++) ins4(ov[j],oi[j],tv,ti);
    }
}

__device__ __forceinline__ void gbar(){
    __threadfence();
    __syncthreads();
    if (threadIdx.x == 0){
        unsigned e = g_epoch;
        if (atomicAdd(&g_cnt, 1u) == NB-1u){
            g_cnt = 0;
            __threadfence();
            g_epoch = e + 1u;
        } else {
            while (g_epoch == e) { __nanosleep(32); }
        }
    }
    __syncthreads();
    __threadfence();
}

__global__ void __launch_bounds__(NT, 1) beam_kernel(
    const float* __restrict__ video, const float* __restrict__ emb,
    const float* __restrict__ Wih_f, const float* __restrict__ Whh_f, const float* __restrict__ b_f,
    const float* __restrict__ Wih_b, const float* __restrict__ b_b,
    const float* __restrict__ dWih, const float* __restrict__ dWhh, const float* __restrict__ db,
    const float* __restrict__ Wcat, const float* __restrict__ bcat,
    const float* __restrict__ Wout, const float* __restrict__ bout,
    float* __restrict__ out, int out_size)
{
    extern __shared__ float4 dyn4[];
    float* dyn = (float*)dyn4;
    float* smem = dyn;
    __shared__ float sm_m[8][KB], sm_s[8][KB];
    __shared__ float scv[8*KB];  __shared__ int sci[8*KB];
    __shared__ int   s_bi2[KB], s_tok[KB];
    __shared__ float s_bp[KB], s_gmax[KB], s_S[KB];

    const int bid = blockIdx.x, tid = threadIdx.x;
    const int wid = tid>>5, lane = tid&31;
    const int gwarp = bid*8 + wid;

    // =============== P0: init + encoder input projections ===============
    {
        int g = bid*NT + tid;
        if (g < KB*(ML+1)) g_tok[0][g] = 1;
        if (g < HH) { g_encH[0][g] = 0.f; g_encC[g] = 0.f; }
    }

    for (int job = bid; job < 168; job += NB){
        if (job < 160){
            const int t0 = (job>>5)*16, j0 = (job&31)*64;
            float* Xs = smem;                // [16][65]
            float* Ws = smem + 16*65;        // [64][65]
            const int jj = tid & 63, tr = tid >> 6;
            float acc[4] = {0.f,0.f,0.f,0.f};
            for (int kc = 0; kc < DIN; kc += 64){
                __syncthreads();
                for (int i = tid; i < 16*64; i += NT){
                    int r = i>>6, kk = i&63;
                    Xs[r*65+kk] = __ldg(&video[(size_t)(t0+r)*DIN + kc+kk]);
                }
                for (int i = tid; i < 64*64; i += NT){
                    int r = i>>6, kk = i&63;
                    Ws[r*65+kk] = __ldg(&Wih_f[(size_t)(j0+r)*DIN + kc+kk]);
                }
                __syncthreads();
                #pragma unroll 8
                for (int kk = 0; kk < 64; kk++){
                    float w = Ws[jj*65+kk];
                    #pragma unroll
                    for (int u = 0; u < 4; u++)
                        acc[u] += Xs[(tr+4*u)*65+kk]*w;
                }
            }
            float bb = __ldg(&b_f[j0+jj]);
            #pragma unroll
            for (int u = 0; u < 4; u++)
                g_Xpre[(size_t)(t0+tr+4*u)*GE + j0+jj] = acc[u] + bb;
            __syncthreads();
        } else {
            const int r0 = (job-160)*256 + wid*32;
            const float4* x4 = (const float4*)(video + (size_t)(TT-1)*DIN);
            for (int rr = 0; rr < 32; rr++){
                int row = r0 + rr;
                const float4* w4 = (const float4*)(Wih_b + (size_t)row*DIN);
                float a = 0.f;
                #pragma unroll 8
                for (int q = 0; q < 32; q++)
                    a += dot4(__ldg(&w4[lane+32*q]), __ldg(&x4[lane+32*q]));
                #pragma unroll
                for (int o = 16; o; o >>= 1) a += __shfl_xor_sync(0xffffffffu,a,o);
                if (lane == 0) g_Gb[row] = a + __ldg(&b_b[row]);
            }
        }
    }
    unsigned e0 = g_epoch_e;
    gbar();

    // =============== P1: forward encoder (80 steps, blocks 0-63) ===============
    if (bid < 64){
        unsigned e = e0;
        for (int t = 0; t < TT; t++){
            const float* hin = g_encH[t&1];
            for (int i = tid; i < HH; i += NT) smem[i] = __ldcg(&hin[i]);
            __syncthreads();
            const int j = bid*8 + wid;
            const float4* h4 = (const float4*)smem;
            float acc[4];
            #pragma unroll
            for (int g = 0; g < 4; g++){
                const float4* w4 = (const float4*)(Whh_f + (size_t)(g*HH + j)*HH);
                float a = 0.f;
                #pragma unroll
                for (int q = 0; q < 4; q++)
                    a += dot4(__ldg(&w4[lane+32*q]), h4[lane+32*q]);
                acc[g] = a;
            }
            #pragma unroll
            for (int o = 16; o; o >>= 1)
                #pragma unroll
                for (int g = 0; g < 4; g++)
                    acc[g] += __shfl_xor_sync(0xffffffffu, acc[g], o);
            if (lane == 0){
                float gi = acc[0] + __ldcg(&g_Xpre[(size_t)t*GE + j]);
                float gf = acc[1] + __ldcg(&g_Xpre[(size_t)t*GE + HH + j]);
                float gg = acc[2] + __ldcg(&g_Xpre[(size_t)t*GE + 2*HH + j]);
                float go = acc[3] + __ldcg(&g_Xpre[(size_t)t*GE + 3*HH + j]);
                float c2 = sigm(gf)*__ldcg(&g_encC[j]) + sigm(gi)*tanhf(gg);
                float h2 = sigm(go)*tanhf(c2);
                g_encC[j] = c2;
                g_encH[(t+1)&1][j] = h2;
            }
            __threadfence();
            __syncthreads();
            if (tid == 0){
                if (atomicAdd(&g_cnt_e, 1u) == 63u){
                    g_cnt_e = 0;
                    __threadfence();
                    g_epoch_e = e + 1u;
                } else {
                    while (g_epoch_e == e) { __nanosleep(32); }
                }
            }
            __syncthreads();
            __threadfence();
            e = e + 1u;
        }
    } else {
        if (tid == 0){
            while ((unsigned)(g_epoch_e - e0) < (unsigned)TT) { __nanosleep(256); }
        }
        __syncthreads();
        __threadfence();
    }
    gbar();

    // =============== P2: decoder init ===============
    {
        int g = bid*NT + tid;
        if (g < HH){
            float hf = __ldcg(&g_encH[0][g]);
            float gi = __ldcg(&g_Gb[g]);
            float gg = __ldcg(&g_Gb[2*HH+g]);
            float go = __ldcg(&g_Gb[3*HH+g]);
            float cb = sigm(gi)*tanhf(gg);
            float hb = sigm(go)*tanhf(cb);
            #pragma unroll
            for (int k = 0; k < KB; k++){
                g_h2[0][k*HD2 + g]      = hf;
                g_h2[0][k*HD2 + HH + g] = hb;
            }
        }
        for (int i = g; i < KB*HD2; i += NB*NT) g_c2[0][i] = 0.f;
    }
    gbar();

    // =============== P3: decoder beam search (20 steps) ===============
    float4* xs = dyn4;             // [4][256] f4
    float4* hs = dyn4 + 1024;      // [4][256] f4

    for (int t = 0; t < ML; t++){
        const int cur = t & 1, nxt = (t+1) & 1;

        // -------- SEL --------
        if (t == 0){
            if (tid < KB){ s_bi2[tid]=tid; s_tok[tid]=1; s_bp[tid]=(tid==0)?1.f:0.f; }
            __syncthreads();
        } else {
            if (wid == 0){
                float tv[4] = {-FLT_MAX,-FLT_MAX,-FLT_MAX,-FLT_MAX};
                int   ti[4] = {0x7fffffff,0x7fffffff,0x7fffffff,0x7fffffff};
                for (int i = lane; i < NB*KB; i += 32)
                    ins4(__ldcg(&g_candv[i]), __ldcg(&g_candi[i]), tv, ti);
                warp_merge4(tv, ti);
                if (lane == 0)
                    #pragma unroll
                    for (int j = 0; j < 4; j++){
                        int idx = ti[j];
                        s_bi2[j] = idx / VV;
                        s_tok[j] = idx - (idx/VV)*VV;
                        s_bp[j]  = tv[j];
                    }
            }
            __syncthreads();
            if (bid == 0 && tid < KB*(ML+1)){
                int kk = tid/(ML+1), col = tid%(ML+1);
                int val = (col == t) ? s_tok[kk]
                                     : g_tok[(t-1)&1][s_bi2[kk]*(ML+1)+col];
                g_tok[t&1][tid] = val;
            }
        }

        // -------- A: decoder LSTM cell --------
        for (int i = tid; i < KB*HD2; i += NT){
            int k = i>>10, j = i&1023;
            ((float*)xs)[i] = __ldg(&emb[(size_t)s_tok[k]*HD2 + j]);
            ((float*)hs)[i] = __ldcg(&g_h2[cur][s_bi2[k]*HD2 + j]);
        }
        __syncthreads();
        for (int j = gwarp; j < HD2; j += NWARP){
            float acc[4][KB];
            #pragma unroll
            for (int g = 0; g < 4; g++)
                #pragma unroll
                for (int k = 0; k < KB; k++) acc[g][k] = 0.f;
            #pragma unroll
            for (int gp = 0; gp < 2; gp++){
                float4 wA[2][8], wB[2][8];
                #pragma unroll
                for (int gg = 0; gg < 2; gg++){
                    const float4* wi_r = (const float4*)(dWih + (size_t)((gp*2+gg)*HD2+j)*HD2);
                    const float4* wh_r = (const float4*)(dWhh + (size_t)((gp*2+gg)*HD2+j)*HD2);
                    #pragma unroll
                    for (int q = 0; q < 8; q++){
                        wA[gg][q] = __ldg(wi_r + lane + 32*q);
                        wB[gg][q] = __ldg(wh_r + lane + 32*q);
                    }
                }
                #pragma unroll
                for (int gg = 0; gg < 2; gg++){
                    const int g = gp*2+gg;
                    #pragma unroll
                    for (int q = 0; q < 8; q++){
                        int m = lane + 32*q;
                        #pragma unroll
                        for (int k = 0; k < KB; k++)
                            acc[g][k] += dot4(wA[gg][q], xs[k*256+m]) + dot4(wB[gg][q], hs[k*256+m]);
                    }
                }
            }
            #pragma unroll
            for (int o = 16; o; o >>= 1)
                #pragma unroll
                for (int g = 0; g < 4; g++)
                    #pragma unroll
                    for (int k = 0; k < KB; k++)
                        acc[g][k] += __shfl_xor_sync(0xffffffffu, acc[g][k], o);
            if (lane == 0){
                float bi_ = __ldg(&db[j]),       bf_ = __ldg(&db[HD2+j]);
                float bg_ = __ldg(&db[2*HD2+j]), bo_ = __ldg(&db[3*HD2+j]);
                #pragma unroll
                for (int k = 0; k < KB; k++){
                    float gi = acc[0][k]+bi_, gf = acc[1][k]+bf_;
                    float gg = acc[2][k]+bg_, go = acc[3][k]+bo_;
                    float cp = __ldcg(&g_c2[cur][s_bi2[k]*HD2 + j]);
                    float c2 = sigm(gf)*cp + sigm(gi)*tanhf(gg);
                    float h2 = sigm(go)*tanhf(c2);
                    g_c2[nxt][k*HD2+j] = c2;
                    g_h2[nxt][k*HD2+j] = h2;
                }
            }
        }
        gbar();

        // -------- B: o = tanh(W_cat @ [h2, x] + b_cat) --------
        for (int i = tid; i < KB*HD2; i += NT) ((float*)hs)[i] = __ldcg(&g_h2[nxt][i]);
        __syncthreads();
        for (int j = gwarp; j < HD2; j += NWARP){
            float acc[KB] = {0.f,0.f,0.f,0.f};
            const float4* wr = (const float4*)(Wcat + (size_t)j*(2*HD2));
            float4 w1[8], w2[8];
            #pragma unroll
            for (int q = 0; q < 8; q++){
                w1[q] = __ldg(&wr[lane + 32*q]);
                w2[q] = __ldg(&wr[256 + lane + 32*q]);
            }
            #pragma unroll
            for (int q = 0; q < 8; q++){
                int m = lane + 32*q;
                #pragma unroll
                for (int k = 0; k < KB; k++)
                    acc[k] += dot4(w1[q], hs[k*256+m]) + dot4(w2[q], xs[k*256+m]);
            }
            #pragma unroll
            for (int o = 16; o; o >>= 1)
                #pragma unroll
                for (int k = 0; k < KB; k++)
                    acc[k] += __shfl_xor_sync(0xffffffffu, acc[k], o);
            if (lane == 0){
                float bb = __ldg(&bcat[j]);
                #pragma unroll
                for (int k = 0; k < KB; k++)
                    g_o[k*HD2+j] = tanhf(acc[k] + bb);
            }
        }
        gbar();

        // -------- C: logits via cp.async double-buffered W_out tiles --------
        {
            float4* os4 = dyn4;                 // 16 KB
            float*  Wb0 = dyn + 4*OS_F4;        // 96 KB
            float*  Wb1 = Wb0 + TR*HD2;         // 96 KB
            for (int i = tid; i < KB*HD2; i += NT) ((float*)os4)[i] = __ldcg(&g_o[i]);
            // issue first tile while os settles (disjoint smem regions)
            {
                int base = bid*TR;
                #pragma unroll 4
                for (int c = tid; c < TR*256; c += NT){
                    int r = c >> 8, off = c & 255;
                    int v = base + r;
                    if (v < VV)
                        cpa16(Wb0 + r*HD2 + off*4, (const float4*)Wout + (size_t)v*256 + off);
                }
                asm volatile("cp.async.commit_group;");
            }
            __syncthreads();
            // per-warp register copy of o (4 beams x 8 chunks)
            float4 osr[KB][8];
            #pragma unroll
            for (int k = 0; k < KB; k++)
                #pragma unroll
                for (int q = 0; q < 8; q++)
                    osr[k][q] = os4[k*256 + lane + 32*q];

            float mw[KB] = {-FLT_MAX,-FLT_MAX,-FLT_MAX,-FLT_MAX};
            float sw[KB] = {0.f,0.f,0.f,0.f};

            int idx = 0;
            for (int it = bid; it < NTILES; it += NB, idx++){
                float* cw = (idx & 1) ? Wb1 : Wb0;
                float* nw = (idx & 1) ? Wb0 : Wb1;
                __syncthreads();                     // prior compute done on nw
                int nt_ = it + NB;
                if (nt_ < NTILES){
                    int base = nt_*TR;
                    #pragma unroll 4
                    for (int c = tid; c < TR*256; c += NT){
                        int r = c >> 8, off = c & 255;
                        int v = base + r;
                        if (v < VV)
                            cpa16(nw + r*HD2 + off*4, (const float4*)Wout + (size_t)v*256 + off);
                    }
                    asm volatile("cp.async.commit_group;");
                    asm volatile("cp.async.wait_group 1;");
                } else {
                    asm volatile("cp.async.wait_group 0;");
                }
                __syncthreads();                     // current tile visible to all

                const int base = it*TR;
                const float4* W0 = (const float4*)cw + (wid*3+0)*256;
                const float4* W1 = (const float4*)cw + (wid*3+1)*256;
                const float4* W2 = (const float4*)cw + (wid*3+2)*256;
                float acc[3][KB];
                #pragma unroll
                for (int r = 0; r < 3; r++)
                    #pragma unroll
                    for (int k = 0; k < KB; k++) acc[r][k] = 0.f;
                #pragma unroll
                for (int q = 0; q < 8; q++){
                    int m = lane + 32*q;
                    float4 w0 = W0[m], w1 = W1[m], w2 = W2[m];
                    #pragma unroll
                    for (int k = 0; k < KB; k++){
                        acc[0][k] += dot4(w0, osr[k][q]);
                        acc[1][k] += dot4(w1, osr[k][q]);
                        acc[2][k] += dot4(w2, osr[k][q]);
                    }
                }
                #pragma unroll
                for (int o = 16; o; o >>= 1)
                    #pragma unroll
                    for (int r = 0; r < 3; r++)
                        #pragma unroll
                        for (int k = 0; k < KB; k++)
                            acc[r][k] += __shfl_xor_sync(0xffffffffu, acc[r][k], o);
                if (lane == 0){
                    #pragma unroll
                    for (int r = 0; r < 3; r++){
                        int v = base + wid*3 + r;
                        if (v < VV){
                            float bo = __ldg(&bout[v]);
                            #pragma unroll
                            for (int k = 0; k < KB; k++){
                                float l = acc[r][k] + bo;
                                g_logits[(size_t)k*VV + v] = l;
                                if (l > mw[k]){ sw[k] = sw[k]*expf(mw[k]-l) + 1.f; mw[k] = l; }
                                else          { sw[k] += expf(l - mw[k]); }
                            }
                        }
                    }
                }
            }
            if (lane == 0)
                #pragma unroll
                for (int k = 0; k < KB; k++){ sm_m[wid][k] = mw[k]; sm_s[wid][k] = sw[k]; }
            __syncthreads();
            if (tid < KB){
                const int k = tid;
                float m = -FLT_MAX, s = 0.f;
                #pragma unroll
                for (int w = 0; w < 8; w++){
                    float mwv = sm_m[w][k], swv = sm_s[w][k];
                    if (mwv > m){ s = s*expf(m-mwv) + swv; m = mwv; }
                    else        { s += swv*expf(mwv-m); }
                }
                g_pmax[bid*KB+k] = m;
                g_psum[bid*KB+k] = s;
            }
        }
        gbar();

        // -------- E: global (m,S); sc=ftz chain; per-block top-4 --------
        if (wid < KB){
            const int k = wid;
            float mloc = -FLT_MAX;
            for (int i = lane; i < NB; i += 32)
                mloc = fmaxf(mloc, __ldcg(&g_pmax[i*KB+k]));
            #pragma unroll
            for (int o = 16; o; o >>= 1) mloc = fmaxf(mloc, __shfl_xor_sync(0xffffffffu, mloc, o));
            float sloc = 0.f;
            for (int i = lane; i < NB; i += 32){
                float mb = __ldcg(&g_pmax[i*KB+k]);
                float sb = __ldcg(&g_psum[i*KB+k]);
                sloc += sb*expf(mb - mloc);
            }
            #pragma unroll
            for (int o = 16; o; o >>= 1) sloc += __shfl_xor_sync(0xffffffffu, sloc, o);
            if (lane == 0){ s_gmax[k] = mloc; s_S[k] = sloc; }
        }
        __syncthreads();
        {
            float tv[4] = {-FLT_MAX,-FLT_MAX,-FLT_MAX,-FLT_MAX};
            int   ti[4] = {0x7fffffff,0x7fffffff,0x7fffffff,0x7fffffff};
            for (int v = bid*NT + tid; v < VV; v += NB*NT){
                #pragma unroll
                for (int k = 0; k < KB; k++){
                    float l  = __ldcg(&g_logits[(size_t)k*VV+v]);
                    float e  = ftz(expf(l - s_gmax[k]));
                    float pf = ftz(__fdiv_rn(e, s_S[k]));
                    float sc = ftz(__fmul_rn(s_bp[k], pf));
                    ins4(sc, k*VV+v, tv, ti);
                }
            }
            warp_merge4(tv, ti);
            if (lane == 0)
                #pragma unroll
                for (int j = 0; j < 4; j++){ scv[wid*4+j]=tv[j]; sci[wid*4+j]=ti[j]; }
            __syncthreads();
            if (tid == 0){
                float bv[4] = {-FLT_MAX,-FLT_MAX,-FLT_MAX,-FLT_MAX};
                int   bix[4] = {0x7fffffff,0x7fffffff,0x7fffffff,0x7fffffff};
                for (int i = 0; i < 32; i++) ins4(scv[i], sci[i], bv, bix);
                #pragma unroll
                for (int j = 0; j < 4; j++){ g_candv[bid*4+j]=bv[j]; g_candi[bid*4+j]=bix[j]; }
            }
        }
        gbar();
    }

    // =============== final selection + output ===============
    if (wid == 0){
        float tv[4] = {-FLT_MAX,-FLT_MAX,-FLT_MAX,-FLT_MAX};
        int   ti[4] = {0x7fffffff,0x7fffffff,0x7fffffff,0x7fffffff};
        for (int i = lane; i < NB*KB; i += 32)
            ins4(__ldcg(&g_candv[i]), __ldcg(&g_candi[i]), tv, ti);
        warp_merge4(tv, ti);
        if (lane == 0)
            #pragma unroll
            for (int j = 0; j < 4; j++){
                int idx = ti[j];
                s_bi2[j] = idx / VV;
                s_tok[j] = idx - (idx/VV)*VV;
                s_bp[j]  = tv[j];
            }
    }
    __syncthreads();
    if (bid == 0){
        if (tid < KB*(ML+1)){
            int kk = tid/(ML+1), col = tid%(ML+1);
            int val = (col == ML) ? s_tok[kk]
                                  : g_tok[(ML-1)&1][s_bi2[kk]*(ML+1)+col];
            out[tid] = (float)val;
        }
        if (out_size >= KB*(ML+1)+KB && tid < KB)
            out[KB*(ML+1)+tid] = s_bp[tid];
    }
}

// ---------------- host ----------------
static int pick_idx(const int* sz, int n, int want, int occ){
    int c = 0;
    for (int i = 0; i < n; i++)
        if (sz[i] == want){ if (c == occ) return i; c++; }
    return -1;
}

extern "C" void kernel_launch(void* const* d_in, const int* in_sizes, int n_in,
                              void* d_out, int out_size)
{
    int iv   = pick_idx(in_sizes, n_in, TT*DIN, 0);
    int ie   = pick_idx(in_sizes, n_in, VV*HD2, 0);
    int iWf  = pick_idx(in_sizes, n_in, GE*DIN, 0);
    int iHf  = pick_idx(in_sizes, n_in, GE*HH, 0);
    int ibf  = pick_idx(in_sizes, n_in, GE, 0);
    int iWb  = pick_idx(in_sizes, n_in, GE*DIN, 1);
    int ibb  = pick_idx(in_sizes, n_in, GE, 1);
    int idW  = pick_idx(in_sizes, n_in, 4*HD2*HD2, 0);
    int idH  = pick_idx(in_sizes, n_in, 4*HD2*HD2, 1);
    int idb  = pick_idx(in_sizes, n_in, 4*HD2, 0);
    int iWc  = pick_idx(in_sizes, n_in, HD2*2*HD2, 0);
    int ibc  = pick_idx(in_sizes, n_in, HD2, 0);
    int iWo  = pick_idx(in_sizes, n_in, VV*HD2, 1);
    int ibo  = pick_idx(in_sizes, n_in, VV, 0);
    if (iv<0||ie<0||iWf<0||iHf<0||ibf<0||iWb<0||ibb<0||idW<0||idH<0||idb<0||iWc<0||ibc<0||iWo<0||ibo<0){
        iv=0; ie=1; iWf=2; iHf=3; ibf=4; iWb=5; ibb=7; idW=8; idH=9; idb=10; iWc=11; ibc=12; iWo=13; ibo=14;
    }
    cudaFuncSetAttribute(beam_kernel,
                         cudaFuncAttributeMaxDynamicSharedMemorySize, DYN_BYTES);
    beam_kernel<<<NB, NT, DYN_BYTES>>>(
        (const float*)d_in[iv],  (const float*)d_in[ie],
        (const float*)d_in[iWf], (const float*)d_in[iHf], (const float*)d_in[ibf],
        (const float*)d_in[iWb], (const float*)d_in[ibb],
        (const float*)d_in[idW], (const float*)d_in[idH], (const float*)d_in[idb],
        (const float*)d_in[iWc], (const float*)d_in[ibc],
        (const float*)d_in[iWo], (const float*)d_in[ibo],
        (float*)d_out, out_size);
}

// round 15
// speedup vs baseline: 1.3399x; 1.3399x over previous
#include <cuda_runtime.h>
#include <cuda_bf16.h>
#include <math.h>
#include <float.h>
#include <stdint.h>

#define TT   80
#define DIN  4096
#define HH   512
#define HD2  1024
#define GE   2048      /* 4*HH  */
#define VV   32000
#define KB   4
#define ML   20
#define NB   264
#define NT   256
#define NWARP (NB*8)   /* 2112 */

// ---------------- device scratch ----------------
__device__ float g_Xpre[TT*GE];
__device__ float g_Gb[GE];
__device__ float g_encH[2][HH];
__device__ float g_encC[HH];
__device__ float g_h2[2][KB*HD2];
__device__ float g_c2[2][KB*HD2];
__device__ float g_o[KB*HD2];
__device__ float g_logits[KB*VV];
__device__ int   g_tok[2][KB*(ML+1)];
__device__ float g_pmax[NB*KB];
__device__ float g_psum[NB*KB];
__device__ float g_candv[NB*KB];
__device__ int   g_candi[NB*KB];
__device__ unsigned g_Wbfu[VV*HD2/2];      // bf16-packed W_out (64 MB)
__device__ unsigned g_cnt = 0;
__device__ volatile unsigned g_epoch = 0;
__device__ unsigned g_cnt_e = 0;
__device__ volatile unsigned g_epoch_e = 0;

// ---------------- helpers ----------------
__device__ __forceinline__ float sigm(float x){ return 1.f/(1.f+expf(-x)); }
__device__ __forceinline__ float dot4(float4 a, float4 b){
    return a.x*b.x + a.y*b.y + a.z*b.z + a.w*b.w;
}
__device__ __forceinline__ float ftz(float x){
    return (fabsf(x) < FLT_MIN) ? 0.f : x;
}
__device__ __forceinline__ unsigned pack_bf(float lo, float hi){
    __nv_bfloat162 h = __floats2bfloat162_rn(lo, hi);
    return *(unsigned*)&h;
}
__device__ __forceinline__ uint4 ldcs_u4(const uint4* p){
    uint4 v;
    asm volatile("ld.global.cs.v4.u32 {%0,%1,%2,%3}, [%4];"
                 : "=r"(v.x), "=r"(v.y), "=r"(v.z), "=r"(v.w) : "l"(p));
    return v;
}

__device__ __forceinline__ bool bet(float v1,int i1,float v2,int i2){
    return (v1 > v2) || (v1 == v2 && i1 < i2);
}
__device__ __forceinline__ void ins4(float v,int i,float tv[4],int ti[4]){
    if (bet(v,i,tv[3],ti[3])){
        tv[3]=v; ti[3]=i;
        if (bet(tv[3],ti[3],tv[2],ti[2])){ float a=tv[2];int b=ti[2]; tv[2]=tv[3];ti[2]=ti[3]; tv[3]=a;ti[3]=b; }
        if (bet(tv[2],ti[2],tv[1],ti[1])){ float a=tv[1];int b=ti[1]; tv[1]=tv[2];ti[1]=ti[2]; tv[2]=a;ti[2]=b; }
        if (bet(tv[1],ti[1],tv[0],ti[0])){ float a=tv[0];int b=ti[0]; tv[0]=tv[1];ti[0]=ti[1]; tv[1]=a;ti[1]=b; }
    }
}
__device__ __forceinline__ void warp_merge4(float tv[4],int ti[4]){
    #pragma unroll
    for (int off=16; off; off>>=1){
        float ov[4]; int oi[4];
        #pragma unroll
        for (int j=0;j<4;j++){
            ov[j]=__shfl_xor_sync(0xffffffffu,tv[j],off);
            oi[j]=__shfl_xor_sync(0xffffffffu,ti[j],off);
        }
        #pragma unroll
        for (int j=0;j<4;j++) ins4(ov[j],oi[j],tv,ti);
    }
}

__device__ __forceinline__ void gbar(){
    __threadfence();
    __syncthreads();
    if (threadIdx.x == 0){
        unsigned e = g_epoch;
        if (atomicAdd(&g_cnt, 1u) == NB-1u){
            g_cnt = 0;
            __threadfence();
            g_epoch = e + 1u;
        } else {
            while (g_epoch == e) { __nanosleep(32); }
        }
    }
    __syncthreads();
    __threadfence();
}

__global__ void __launch_bounds__(NT, 2) beam_kernel(
    const float* __restrict__ video, const float* __restrict__ emb,
    const float* __restrict__ Wih_f, const float* __restrict__ Whh_f, const float* __restrict__ b_f,
    const float* __restrict__ Wih_b, const float* __restrict__ b_b,
    const float* __restrict__ dWih, const float* __restrict__ dWhh, const float* __restrict__ db,
    const float* __restrict__ Wcat, const float* __restrict__ bcat,
    const float* __restrict__ Wout, const float* __restrict__ bout,
    float* __restrict__ out, int out_size)
{
    __shared__ float4 smem4[2048];           // 32 KB staging
    float* smem = (float*)smem4;
    __shared__ float sm_m[8][KB], sm_s[8][KB];
    __shared__ float scv[8*KB];  __shared__ int sci[8*KB];
    __shared__ int   s_bi2[KB], s_tok[KB];
    __shared__ float s_bp[KB], s_gmax[KB], s_S[KB];

    const int bid = blockIdx.x, tid = threadIdx.x;
    const int wid = tid>>5, lane = tid&31;
    const int gwarp = bid*8 + wid;

    // =============== P0: init + W_out->bf16 + encoder input projections ===============
    {
        int g = bid*NT + tid;
        if (g < KB*(ML+1)) g_tok[0][g] = 1;
        if (g < HH) { g_encH[0][g] = 0.f; g_encC[g] = 0.f; }
    }
    // bf16 conversion of W_out (once)
    {
        const int NG = VV*HD2/8;             // 4,096,000 uint4 groups
        for (int g = bid*NT + tid; g < NG; g += NB*NT){
            const float4* src = (const float4*)Wout + 2*(size_t)g;
            float4 a = __ldcs(src), b = __ldcs(src+1);
            uint4 w;
            w.x = pack_bf(a.x, a.y);
            w.y = pack_bf(a.z, a.w);
            w.z = pack_bf(b.x, b.y);
            w.w = pack_bf(b.z, b.w);
            ((uint4*)g_Wbfu)[g] = w;
        }
    }

    for (int job = bid; job < 168; job += NB){
        if (job < 160){
            const int t0 = (job>>5)*16, j0 = (job&31)*64;
            float* Xs = smem;                // [16][65]
            float* Ws = smem + 16*65;        // [64][65]
            const int jj = tid & 63, tr = tid >> 6;
            float acc[4] = {0.f,0.f,0.f,0.f};
            for (int kc = 0; kc < DIN; kc += 64){
                __syncthreads();
                for (int i = tid; i < 16*64; i += NT){
                    int r = i>>6, kk = i&63;
                    Xs[r*65+kk] = __ldg(&video[(size_t)(t0+r)*DIN + kc+kk]);
                }
                for (int i = tid; i < 64*64; i += NT){
                    int r = i>>6, kk = i&63;
                    Ws[r*65+kk] = __ldg(&Wih_f[(size_t)(j0+r)*DIN + kc+kk]);
                }
                __syncthreads();
                #pragma unroll 8
                for (int kk = 0; kk < 64; kk++){
                    float w = Ws[jj*65+kk];
                    #pragma unroll
                    for (int u = 0; u < 4; u++)
                        acc[u] += Xs[(tr+4*u)*65+kk]*w;
                }
            }
            float bb = __ldg(&b_f[j0+jj]);
            #pragma unroll
            for (int u = 0; u < 4; u++)
                g_Xpre[(size_t)(t0+tr+4*u)*GE + j0+jj] = acc[u] + bb;
            __syncthreads();
        } else {
            const int r0 = (job-160)*256 + wid*32;
            const float4* x4 = (const float4*)(video + (size_t)(TT-1)*DIN);
            for (int rr = 0; rr < 32; rr++){
                int row = r0 + rr;
                const float4* w4 = (const float4*)(Wih_b + (size_t)row*DIN);
                float a = 0.f;
                #pragma unroll 8
                for (int q = 0; q < 32; q++)
                    a += dot4(__ldg(&w4[lane+32*q]), __ldg(&x4[lane+32*q]));
                #pragma unroll
                for (int o = 16; o; o >>= 1) a += __shfl_xor_sync(0xffffffffu,a,o);
                if (lane == 0) g_Gb[row] = a + __ldg(&b_b[row]);
            }
        }
    }
    unsigned e0 = g_epoch_e;
    gbar();

    // =============== P1: forward encoder (80 steps, blocks 0-63 only) ===============
    if (bid < 64){
        unsigned e = e0;
        for (int t = 0; t < TT; t++){
            const float* hin = g_encH[t&1];
            for (int i = tid; i < HH; i += NT) smem[i] = __ldcg(&hin[i]);
            __syncthreads();
            const int j = bid*8 + wid;
            const float4* h4 = (const float4*)smem;
            float acc[4];
            #pragma unroll
            for (int g = 0; g < 4; g++){
                const float4* w4 = (const float4*)(Whh_f + (size_t)(g*HH + j)*HH);
                float a = 0.f;
                #pragma unroll
                for (int q = 0; q < 4; q++)
                    a += dot4(__ldg(&w4[lane+32*q]), h4[lane+32*q]);
                acc[g] = a;
            }
            #pragma unroll
            for (int o = 16; o; o >>= 1)
                #pragma unroll
                for (int g = 0; g < 4; g++)
                    acc[g] += __shfl_xor_sync(0xffffffffu, acc[g], o);
            if (lane == 0){
                float gi = acc[0] + __ldcg(&g_Xpre[(size_t)t*GE + j]);
                float gf = acc[1] + __ldcg(&g_Xpre[(size_t)t*GE + HH + j]);
                float gg = acc[2] + __ldcg(&g_Xpre[(size_t)t*GE + 2*HH + j]);
                float go = acc[3] + __ldcg(&g_Xpre[(size_t)t*GE + 3*HH + j]);
                float c2 = sigm(gf)*__ldcg(&g_encC[j]) + sigm(gi)*tanhf(gg);
                float h2 = sigm(go)*tanhf(c2);
                g_encC[j] = c2;
                g_encH[(t+1)&1][j] = h2;
            }
            __threadfence();
            __syncthreads();
            if (tid == 0){
                if (atomicAdd(&g_cnt_e, 1u) == 63u){
                    g_cnt_e = 0;
                    __threadfence();
                    g_epoch_e = e + 1u;
                } else {
                    while (g_epoch_e == e) { __nanosleep(32); }
                }
            }
            __syncthreads();
            __threadfence();
            e = e + 1u;
        }
    } else {
        if (tid == 0){
            while ((unsigned)(g_epoch_e - e0) < (unsigned)TT) { __nanosleep(256); }
        }
        __syncthreads();
        __threadfence();
    }
    gbar();

    // =============== P2: decoder init ===============
    {
        int g = bid*NT + tid;
        if (g < HH){
            float hf = __ldcg(&g_encH[0][g]);
            float gi = __ldcg(&g_Gb[g]);
            float gg = __ldcg(&g_Gb[2*HH+g]);
            float go = __ldcg(&g_Gb[3*HH+g]);
            float cb = sigm(gi)*tanhf(gg);
            float hb = sigm(go)*tanhf(cb);
            #pragma unroll
            for (int k = 0; k < KB; k++){
                g_h2[0][k*HD2 + g]      = hf;
                g_h2[0][k*HD2 + HH + g] = hb;
            }
        }
        for (int i = g; i < KB*HD2; i += NB*NT) g_c2[0][i] = 0.f;
    }
    gbar();

    // =============== P3: decoder beam search (20 steps) ===============
    float4* xs = smem4;            // [4][256] f4
    float4* hs = smem4 + 4*256;    // [4][256] f4

    for (int t = 0; t < ML; t++){
        const int cur = t & 1, nxt = (t+1) & 1;

        // -------- SEL --------
        if (t == 0){
            if (tid < KB){ s_bi2[tid]=tid; s_tok[tid]=1; s_bp[tid]=(tid==0)?1.f:0.f; }
            __syncthreads();
        } else {
            if (wid == 0){
                float tv[4] = {-FLT_MAX,-FLT_MAX,-FLT_MAX,-FLT_MAX};
                int   ti[4] = {0x7fffffff,0x7fffffff,0x7fffffff,0x7fffffff};
                for (int i = lane; i < NB*KB; i += 32)
                    ins4(__ldcg(&g_candv[i]), __ldcg(&g_candi[i]), tv, ti);
                warp_merge4(tv, ti);
                if (lane == 0)
                    #pragma unroll
                    for (int j = 0; j < 4; j++){
                        int idx = ti[j];
                        s_bi2[j] = idx / VV;
                        s_tok[j] = idx - (idx/VV)*VV;
                        s_bp[j]  = tv[j];
                    }
            }
            __syncthreads();
            if (bid == 0 && tid < KB*(ML+1)){
                int kk = tid/(ML+1), col = tid%(ML+1);
                int val = (col == t) ? s_tok[kk]
                                     : g_tok[(t-1)&1][s_bi2[kk]*(ML+1)+col];
                g_tok[t&1][tid] = val;
            }
        }

        // -------- A: decoder LSTM cell --------
        for (int i = tid; i < KB*HD2; i += NT){
            int k = i>>10, j = i&1023;
            ((float*)xs)[i] = __ldg(&emb[(size_t)s_tok[k]*HD2 + j]);
            ((float*)hs)[i] = __ldcg(&g_h2[cur][s_bi2[k]*HD2 + j]);
        }
        __syncthreads();
        for (int j = gwarp; j < HD2; j += NWARP){
            float acc[4][KB];
            #pragma unroll
            for (int g = 0; g < 4; g++)
                #pragma unroll
                for (int k = 0; k < KB; k++) acc[g][k] = 0.f;
            #pragma unroll 2
            for (int q = 0; q < 8; q++){
                int m = lane + 32*q;
                #pragma unroll
                for (int g = 0; g < 4; g++){
                    float4 wi = __ldg((const float4*)(dWih + (size_t)(g*HD2+j)*HD2) + m);
                    float4 wh = __ldg((const float4*)(dWhh + (size_t)(g*HD2+j)*HD2) + m);
                    #pragma unroll
                    for (int k = 0; k < KB; k++)
                        acc[g][k] += dot4(wi, xs[k*256+m]) + dot4(wh, hs[k*256+m]);
                }
            }
            #pragma unroll
            for (int o = 16; o; o >>= 1)
                #pragma unroll
                for (int g = 0; g < 4; g++)
                    #pragma unroll
                    for (int k = 0; k < KB; k++)
                        acc[g][k] += __shfl_xor_sync(0xffffffffu, acc[g][k], o);
            if (lane == 0){
                float bi_ = __ldg(&db[j]),       bf_ = __ldg(&db[HD2+j]);
                float bg_ = __ldg(&db[2*HD2+j]), bo_ = __ldg(&db[3*HD2+j]);
                #pragma unroll
                for (int k = 0; k < KB; k++){
                    float gi = acc[0][k]+bi_, gf = acc[1][k]+bf_;
                    float gg = acc[2][k]+bg_, go = acc[3][k]+bo_;
                    float cp = __ldcg(&g_c2[cur][s_bi2[k]*HD2 + j]);
                    float c2 = sigm(gf)*cp + sigm(gi)*tanhf(gg);
                    float h2 = sigm(go)*tanhf(c2);
                    g_c2[nxt][k*HD2+j] = c2;
                    g_h2[nxt][k*HD2+j] = h2;
                }
            }
        }
        gbar();

        // -------- B: o = tanh(W_cat @ [h2, x] + b_cat) --------
        for (int i = tid; i < KB*HD2; i += NT) ((float*)hs)[i] = __ldcg(&g_h2[nxt][i]);
        __syncthreads();
        for (int j = gwarp; j < HD2; j += NWARP){
            float acc[KB] = {0.f,0.f,0.f,0.f};
            const float4* wr = (const float4*)(Wcat + (size_t)j*(2*HD2));
            #pragma unroll 2
            for (int q = 0; q < 8; q++){
                int m = lane + 32*q;
                float4 w1 = __ldg(&wr[m]);
                float4 w2 = __ldg(&wr[256+m]);
                #pragma unroll
                for (int k = 0; k < KB; k++)
                    acc[k] += dot4(w1, hs[k*256+m]) + dot4(w2, xs[k*256+m]);
            }
            #pragma unroll
            for (int o = 16; o; o >>= 1)
                #pragma unroll
                for (int k = 0; k < KB; k++)
                    acc[k] += __shfl_xor_sync(0xffffffffu, acc[k], o);
            if (lane == 0){
                float bb = __ldg(&bcat[j]);
                #pragma unroll
                for (int k = 0; k < KB; k++)
                    g_o[k*HD2+j] = tanhf(acc[k] + bb);
            }
        }
        gbar();

        // -------- C: logits from bf16 W_out (4 rows/warp) + online (max,expsum) --------
        float4* os = smem4;   // [4][256]
        for (int i = tid; i < KB*HD2; i += NT) ((float*)os)[i] = __ldcg(&g_o[i]);
        __syncthreads();
        {
            float mw[KB] = {-FLT_MAX,-FLT_MAX,-FLT_MAX,-FLT_MAX};
            float sw[KB] = {0.f,0.f,0.f,0.f};
            for (int v0 = gwarp*4; v0 < VV; v0 += NWARP*4){
                float acc[4][KB];
                #pragma unroll
                for (int r = 0; r < 4; r++)
                    #pragma unroll
                    for (int k = 0; k < KB; k++) acc[r][k] = 0.f;
                #pragma unroll
                for (int q = 0; q < 4; q++){
                    int m = lane + 32*q;             // uint4 index (8 elems each)
                    float4 oa[KB], ob[KB];
                    #pragma unroll
                    for (int k = 0; k < KB; k++){
                        oa[k] = os[k*256 + 2*m];
                        ob[k] = os[k*256 + 2*m + 1];
                    }
                    #pragma unroll
                    for (int r = 0; r < 4; r++){
                        uint4 w = ldcs_u4((const uint4*)g_Wbfu + (size_t)(v0+r)*128 + m);
                        float c0 = __uint_as_float(w.x << 16);
                        float c1 = __uint_as_float(w.x & 0xffff0000u);
                        float c2 = __uint_as_float(w.y << 16);
                        float c3 = __uint_as_float(w.y & 0xffff0000u);
                        float c4 = __uint_as_float(w.z << 16);
                        float c5 = __uint_as_float(w.z & 0xffff0000u);
                        float c6 = __uint_as_float(w.w << 16);
                        float c7 = __uint_as_float(w.w & 0xffff0000u);
                        #pragma unroll
                        for (int k = 0; k < KB; k++){
                            acc[r][k] += c0*oa[k].x + c1*oa[k].y + c2*oa[k].z + c3*oa[k].w
                                       + c4*ob[k].x + c5*ob[k].y + c6*ob[k].z + c7*ob[k].w;
                        }
                    }
                }
                #pragma unroll
                for (int o = 16; o; o >>= 1)
                    #pragma unroll
                    for (int r = 0; r < 4; r++)
                        #pragma unroll
                        for (int k = 0; k < KB; k++)
                            acc[r][k] += __shfl_xor_sync(0xffffffffu, acc[r][k], o);
                if (lane == 0){
                    #pragma unroll
                    for (int r = 0; r < 4; r++){
                        float bo = __ldg(&bout[v0+r]);
                        #pragma unroll
                        for (int k = 0; k < KB; k++){
                            float l = acc[r][k] + bo;
                            g_logits[(size_t)k*VV + v0 + r] = l;
                            if (l > mw[k]){ sw[k] = sw[k]*expf(mw[k]-l) + 1.f; mw[k] = l; }
                            else          { sw[k] += expf(l - mw[k]); }
                        }
                    }
                }
            }
            if (lane == 0)
                #pragma unroll
                for (int k = 0; k < KB; k++){ sm_m[wid][k] = mw[k]; sm_s[wid][k] = sw[k]; }
            __syncthreads();
            if (tid < KB){
                const int k = tid;
                float m = -FLT_MAX, s = 0.f;
                #pragma unroll
                for (int w = 0; w < 8; w++){
                    float mwv = sm_m[w][k], swv = sm_s[w][k];
                    if (mwv > m){ s = s*expf(m-mwv) + swv; m = mwv; }
                    else        { s += swv*expf(mwv-m); }
                }
                g_pmax[bid*KB+k] = m;
                g_psum[bid*KB+k] = s;
            }
        }
        gbar();

        // -------- E: global (m,S); sc=ftz chain; per-block top-4 --------
        if (wid < KB){
            const int k = wid;
            float mloc = -FLT_MAX;
            for (int i = lane; i < NB; i += 32)
                mloc = fmaxf(mloc, __ldcg(&g_pmax[i*KB+k]));
            #pragma unroll
            for (int o = 16; o; o >>= 1) mloc = fmaxf(mloc, __shfl_xor_sync(0xffffffffu, mloc, o));
            float sloc = 0.f;
            for (int i = lane; i < NB; i += 32){
                float mb = __ldcg(&g_pmax[i*KB+k]);
                float sb = __ldcg(&g_psum[i*KB+k]);
                sloc += sb*expf(mb - mloc);
            }
            #pragma unroll
            for (int o = 16; o; o >>= 1) sloc += __shfl_xor_sync(0xffffffffu, sloc, o);
            if (lane == 0){ s_gmax[k] = mloc; s_S[k] = sloc; }
        }
        __syncthreads();
        {
            float tv[4] = {-FLT_MAX,-FLT_MAX,-FLT_MAX,-FLT_MAX};
            int   ti[4] = {0x7fffffff,0x7fffffff,0x7fffffff,0x7fffffff};
            for (int v = bid*NT + tid; v < VV; v += NB*NT){
                #pragma unroll
                for (int k = 0; k < KB; k++){
                    float l  = __ldcg(&g_logits[(size_t)k*VV+v]);
                    float e  = ftz(expf(l - s_gmax[k]));
                    float pf = ftz(__fdiv_rn(e, s_S[k]));
                    float sc = ftz(__fmul_rn(s_bp[k], pf));
                    ins4(sc, k*VV+v, tv, ti);
                }
            }
            warp_merge4(tv, ti);
            if (lane == 0)
                #pragma unroll
                for (int j = 0; j < 4; j++){ scv[wid*4+j]=tv[j]; sci[wid*4+j]=ti[j]; }
            __syncthreads();
            if (tid == 0){
                float bv[4] = {-FLT_MAX,-FLT_MAX,-FLT_MAX,-FLT_MAX};
                int   bix[4] = {0x7fffffff,0x7fffffff,0x7fffffff,0x7fffffff};
                for (int i = 0; i < 32; i++) ins4(scv[i], sci[i], bv, bix);
                #pragma unroll
                for (int j = 0; j < 4; j++){ g_candv[bid*4+j]=bv[j]; g_candi[bid*4+j]=bix[j]; }
            }
        }
        gbar();
    }

    // =============== final selection + output ===============
    if (wid == 0){
        float tv[4] = {-FLT_MAX,-FLT_MAX,-FLT_MAX,-FLT_MAX};
        int   ti[4] = {0x7fffffff,0x7fffffff,0x7fffffff,0x7fffffff};
        for (int i = lane; i < NB*KB; i += 32)
            ins4(__ldcg(&g_candv[i]), __ldcg(&g_candi[i]), tv, ti);
        warp_merge4(tv, ti);
        if (lane == 0)
            #pragma unroll
            for (int j = 0; j < 4; j++){
                int idx = ti[j];
                s_bi2[j] = idx / VV;
                s_tok[j] = idx - (idx/VV)*VV;
                s_bp[j]  = tv[j];
            }
    }
    __syncthreads();
    if (bid == 0){
        if (tid < KB*(ML+1)){
            int kk = tid/(ML+1), col = tid%(ML+1);
            int val = (col == ML) ? s_tok[kk]
                                  : g_tok[(ML-1)&1][s_bi2[kk]*(ML+1)+col];
            out[tid] = (float)val;
        }
        if (out_size >= KB*(ML+1)+KB && tid < KB)
            out[KB*(ML+1)+tid] = s_bp[tid];
    }
}

// ---------------- host ----------------
static int pick_idx(const int* sz, int n, int want, int occ){
    int c = 0;
    for (int i = 0; i < n; i++)
        if (sz[i] == want){ if (c == occ) return i; c++; }
    return -1;
}

extern "C" void kernel_launch(void* const* d_in, const int* in_sizes, int n_in,
                              void* d_out, int out_size)
{
    int iv   = pick_idx(in_sizes, n_in, TT*DIN, 0);
    int ie   = pick_idx(in_sizes, n_in, VV*HD2, 0);
    int iWf  = pick_idx(in_sizes, n_in, GE*DIN, 0);
    int iHf  = pick_idx(in_sizes, n_in, GE*HH, 0);
    int ibf  = pick_idx(in_sizes, n_in, GE, 0);
    int iWb  = pick_idx(in_sizes, n_in, GE*DIN, 1);
    int ibb  = pick_idx(in_sizes, n_in, GE, 1);
    int idW  = pick_idx(in_sizes, n_in, 4*HD2*HD2, 0);
    int idH  = pick_idx(in_sizes, n_in, 4*HD2*HD2, 1);
    int idb  = pick_idx(in_sizes, n_in, 4*HD2, 0);
    int iWc  = pick_idx(in_sizes, n_in, HD2*2*HD2, 0);
    int ibc  = pick_idx(in_sizes, n_in, HD2, 0);
    int iWo  = pick_idx(in_sizes, n_in, VV*HD2, 1);
    int ibo  = pick_idx(in_sizes, n_in, VV, 0);
    if (iv<0||ie<0||iWf<0||iHf<0||ibf<0||iWb<0||ibb<0||idW<0||idH<0||idb<0||iWc<0||ibc<0||iWo<0||ibo<0){
        iv=0; ie=1; iWf=2; iHf=3; ibf=4; iWb=5; ibb=7; idW=8; idH=9; idb=10; iWc=11; ibc=12; iWo=13; ibo=14;
    }
    beam_kernel<<<NB, NT>>>(
        (const float*)d_in[iv],  (const float*)d_in[ie],
        (const float*)d_in[iWf], (const float*)d_in[iHf], (const float*)d_in[ibf],
        (const float*)d_in[iWb], (const float*)d_in[ibb],
        (const float*)d_in[idW], (const float*)d_in[idH], (const float*)d_in[idb],
        (const float*)d_in[iWc], (const float*)d_in[ibc],
        (const float*)d_in[iWo], (const float*)d_in[ibo],
        (float*)d_out, out_size);
}